// round 17
// baseline (speedup 1.0000x reference)
#include <cuda_runtime.h>
#include <math.h>

// ProCoUNLoss — two kernels with PDL; proco reduce uses the exact expansion
//   x^2 = Sum(p^2) [per-class, DS] + 2*dot(p,f) + Sum(f^2) [per-row]
// (drops only the incoherent fl(p+f) rounding terms, ~0.04u*kappa on x).
// x and L bit-exact; lnu ~2e-6 incl. the reference's Miller contamination.

namespace {
constexpr int NB   = 256;
constexpr int DD   = 128;
constexpr int CC   = 1000;
constexpr int CPAD = 1024;
constexpr int TN   = 16;   // n tile (2 outputs/thread)
constexpr int TC   = 16;   // c tile
}

__device__ float g_proto[CPAD * DD];  // fl(kappa * Ave_norm), zero padded
__device__ float g_ph[CPAD];          // DS hi of Sum(proto^2)
__device__ float g_pl[CPAD];          // DS lo of Sum(proto^2)
__device__ float g_fsq[NB];           // Sum(feat^2) per row

// ---------- packed f32x2 helpers ----------
__device__ __forceinline__ unsigned long long fma2(unsigned long long a,
                                                   unsigned long long b,
                                                   unsigned long long c) {
    unsigned long long r;
    asm("fma.rn.f32x2 %0, %1, %2, %3;" : "=l"(r) : "l"(a), "l"(b), "l"(c));
    return r;
}
__device__ __forceinline__ void unpack2(unsigned long long v, float& lo, float& hi) {
    unsigned int l, h;
    asm("mov.b64 {%0, %1}, %2;" : "=r"(l), "=r"(h) : "l"(v));
    lo = __uint_as_float(l); hi = __uint_as_float(h);
}

// rcp with one Newton step: ~1 ulp (MUFU.RCP + 2 fma)
__device__ __forceinline__ float rcp1(float b) {
    float r;
    asm("rcp.approx.ftz.f32 %0, %1;" : "=f"(r) : "f"(b));
    float e = __fmaf_rn(-b, r, 1.0f);
    return __fmaf_rn(r, e, r);
}

// TwoSum: a+b = s + e exactly.
__device__ __forceinline__ void two_sum(float a, float b, float& s, float& e) {
    s = __fadd_rn(a, b);
    float t = __fsub_rn(s, a);
    e = __fadd_rn(__fsub_rn(a, __fsub_rn(s, t)), __fsub_rn(b, t));
}

// ---------- double-single log (for L, which needs bit-exactness) ----------
__device__ __forceinline__ float2 ds_log_core(float mh, float ef) {
    float ah = __fadd_rn(mh, -1.0f);               // exact (Sterbenz)
    float bh = __fadd_rn(mh, 1.0f);
    float tb = __fsub_rn(bh, 1.0f);                // TwoSum residual for m+1
    float bl = __fadd_rn(__fsub_rn(1.0f, __fsub_rn(bh, tb)), __fsub_rn(mh, tb));
    float rb = rcp1(bh);
    float uh = __fmul_rn(ah, rb);                  // ~(m-1)/(m+1); residual fixes
    float rr = __fmaf_rn(-uh, bh, ah);             // exact defect
    rr = __fadd_rn(rr, -__fmul_rn(uh, bl));
    float ul = __fmul_rn(rr, rb);
    float u2 = __fmul_rn(uh, uh);                  // atanh series to u^9
    float p  = u2 * __fmaf_rn(u2, __fmaf_rn(u2, __fmaf_rn(u2, 0.11111111f,
                    0.14285715f), 0.2f), 0.33333334f);
    float lnmh = __fmul_rn(2.0f, uh);              // exact
    float lnml = __fmaf_rn(lnmh, p, __fmul_rn(2.0f, ul));
    const float LN2H = 0.6931471824645996f;
    const float LN2L = -1.9046542e-9f;
    float eh = __fmul_rn(ef, LN2H);
    float el = __fmaf_rn(ef, LN2H, -eh);
    el = __fmaf_rn(ef, LN2L, el);
    float sh, sl;
    two_sum(eh, lnmh, sh, sl);
    return make_float2(sh, __fadd_rn(sl, __fadd_rn(el, lnml)));
}

__device__ __forceinline__ float ds_log_f32(float x) {  // fl32(log(x))
    int ix = __float_as_int(x);
    int e  = ((ix >> 23) & 255) - 127;
    float m = __int_as_float((ix & 0x007fffff) | 0x3f800000);
    if (m > 1.4142135f) { m *= 0.5f; e += 1; }
    float2 r = ds_log_core(m, (float)e);
    return __fadd_rn(r.x, r.y);
}

// log1p(v), v in (0.02, 0.9]: 2*atanh(u), u=v/(2+v), series to u^11 (~2e-8)
__device__ __forceinline__ float log1p_v(float v) {
    float u  = __fmul_rn(v, rcp1(__fadd_rn(2.0f, v)));
    float u2 = __fmul_rn(u, u);
    float p  = __fmaf_rn(u2, __fmaf_rn(u2, __fmaf_rn(u2, __fmaf_rn(u2,
                 0.09090909f, 0.11111111f), 0.14285715f), 0.2f), 0.33333334f);
    return __fmul_rn(__fadd_rn(u, u), __fmaf_rn(u2, p, 1.0f));
}

// log1p(z), z in [0, 0.19]: series to z^7 (abs err < 2e-7)
__device__ __forceinline__ float log1p_small(float z) {
    float r = __fmaf_rn(z, 0.14285715f, -0.16666667f);
    r = __fmaf_rn(z, r, 0.2f);
    r = __fmaf_rn(z, r, -0.25f);
    r = __fmaf_rn(z, r, 0.33333334f);
    r = __fmaf_rn(z, r, -0.5f);
    r = __fmaf_rn(z, r, 1.0f);
    return __fmul_rn(z, r);
}

// p(t) = u1(t)/63 + u2(t)/63^2 + u3(t)/63^3  (Debye u-polynomials)
__device__ __forceinline__ float pser_f(float t) {
    float t2 = t * t;
    float a = t * (3.0f - 5.0f * t2) * (1.0f / 1512.0f);
    float b = t2 * (81.0f + t2 * (-462.0f + 385.0f * t2)) * 2.1870954e-7f;
    float c = t2 * t * (30375.0f + t2 * (-369603.0f + t2 * (765765.0f - 425425.0f * t2)))
              * 9.643249e-12f;
    return a + b + c;
}

// Miller-recurrence contamination of the reference (start M=126):
// log1p(-rho63) - log1p(rho0). lp63 = log1p((63+dw63)/x) from caller.
__device__ __forceinline__ float miller_corr(float x, float w63, float lp63) {
    float w127  = __fsqrt_rn(__fmaf_rn(x, x, 16129.0f));
    float dw127 = __fdividef(16129.0f, __fadd_rn(w127, x));
    float L127  = __logf(__fadd_rn(1.0f,
                     __fdividef(__fadd_rn(127.0f, dw127), x)));
    float g63 = __fmaf_rn(-254.0f, L127, __fmaf_rn(126.0f, lp63,
                  2.0f * __fdividef(12160.0f, __fadd_rn(w127, w63))));
    float g0  = __fmaf_rn(-254.0f, L127, __fadd_rn(dw127, dw127));
    float r63 = __expf(g63);   // underflow to 0 at small x: correct
    float r0  = __expf(g0);
    return -(r63 + r0) - 0.5f * (r63 * r63 - r0 * r0);
}

// Per-element epilogue: (s, kc) = DS of x^2 -> x -> lnu -> ref association.
__device__ __forceinline__ float epilogue(float s, float kc, float lc) {
    // x = f32(sqrt(s+kc)) via Newton-refined sqrt
    float r0  = __fsqrt_rn(s);
    float e1  = __fmaf_rn(r0, r0, -s);
    float num = __fsub_rn(e1, kc);
    float x   = __fsub_rn(r0, __fmul_rn(__fmul_rn(0.5f, num), rcp1(r0)));

    float w   = __fsqrt_rn(__fmaf_rn(x, x, 3969.0f));
    float dwx = __fmul_rn(3969.0f, rcp1(__fadd_rn(w, x)));  // w - x, stable
    float rx  = rcp1(x);
    float v   = __fmul_rn(__fadd_rn(63.0f, dwx), rx);

    float lp  = log1p_v(v);                            // log1p(v)
    float L   = ds_log_f32(x);                         // bit-exact f32 log

    float hlw = 0.5f * __fadd_rn(L, log1p_small(__fmul_rn(dwx, rx)));
    float pp  = pser_f(__fdividef(63.0f, w));
    float lnS = __fmaf_rn(-0.5f * pp, pp, pp);         // log1p(pp)
    float corr = miller_corr(x, w, lp);

    // lnu = dwx - 63*lp - hlw - 0.5*log(2pi) + lnS + corr
    float lnu = __fmaf_rn(-63.0f, lp, dwx);
    lnu = __fsub_rn(lnu, hlw);
    lnu = __fadd_rn(lnu, -0.91893853f);
    lnu = __fadd_rn(lnu, lnS);
    lnu = __fadd_rn(lnu, corr);

    // Reference's f32 association: ((lnu + x) - 63*L) - logc
    return __fsub_rn(__fsub_rn(__fadd_rn(lnu, x), __fmul_rn(63.0f, L)), lc);
}

// Setup: warp per class (gid < CPAD) computes exact f64 tree norm, Markstein
// division, and DS Sum(proto^2); warp per row (gid >= CPAD) computes fsq.
__global__ void setup_kernel(const float* __restrict__ Ave,
                             const float* __restrict__ kappa,
                             const float* __restrict__ feat) {
    const int w    = threadIdx.x >> 5;
    const int lane = threadIdx.x & 31;
    const int gid  = blockIdx.x * 8 + w;

    if (gid < CC) {
        const int c = gid;
        float r0 = Ave[c * DD + lane];
        float r1 = Ave[c * DD + lane + 32];
        float r2 = Ave[c * DD + lane + 64];
        float r3 = Ave[c * DD + lane + 96];
        double s = (double)__fmul_rn(r0, r0);
        s += (double)__fmul_rn(r1, r1);
        s += (double)__fmul_rn(r2, r2);
        s += (double)__fmul_rn(r3, r3);
        #pragma unroll
        for (int off = 16; off; off >>= 1)
            s += __shfl_xor_sync(0xffffffffu, s, off);
        float nrm = fmaxf((float)sqrt(s), 1e-12f);
        float kap = kappa[c];
        float rh  = __frcp_rn(nrm);
        float p0, p1, p2, p3;
        #define MDIV(a, p) { float q0 = __fmul_rn((a), rh);                     \
            float e = __fmaf_rn(-nrm, q0, (a));                                 \
            float q = __fmaf_rn(e, rh, q0);                                     \
            p = __fmul_rn(kap, q); }
        MDIV(r0, p0) MDIV(r1, p1) MDIV(r2, p2) MDIV(r3, p3)
        #undef MDIV
        g_proto[c * DD + lane]      = p0;
        g_proto[c * DD + lane + 32] = p1;
        g_proto[c * DD + lane + 64] = p2;
        g_proto[c * DD + lane + 96] = p3;
        // exact Sum(proto^2) in f64 -> DS
        double s2 = (double)p0 * (double)p0;
        s2 += (double)p1 * (double)p1;
        s2 += (double)p2 * (double)p2;
        s2 += (double)p3 * (double)p3;
        #pragma unroll
        for (int off = 16; off; off >>= 1)
            s2 += __shfl_xor_sync(0xffffffffu, s2, off);
        if (lane == 0) {
            float ph = (float)s2;
            g_ph[c] = ph;
            g_pl[c] = (float)(s2 - (double)ph);
        }
    } else if (gid < CPAD) {
        const int c = gid;
        #pragma unroll
        for (int j = 0; j < 4; ++j)
            g_proto[c * DD + lane + 32 * j] = 0.0f;
        if (lane == 0) { g_ph[c] = 3969.0f; g_pl[c] = 0.0f; }  // benign
    } else {
        const int n = gid - CPAD;          // 0..255
        float f0 = feat[n * DD + lane];
        float f1 = feat[n * DD + lane + 32];
        float f2 = feat[n * DD + lane + 64];
        float f3 = feat[n * DD + lane + 96];
        double s = (double)f0 * (double)f0;
        s += (double)f1 * (double)f1;
        s += (double)f2 * (double)f2;
        s += (double)f3 * (double)f3;
        #pragma unroll
        for (int off = 16; off; off >>= 1)
            s += __shfl_xor_sync(0xffffffffu, s, off);
        if (lane == 0) g_fsq[n] = (float)s;
    }
    // PDL: this block's global stores are done; let dependents proceed.
    asm volatile("griddepcontrol.launch_dependents;");
}

// 16n x 16c tile, 128 threads, 2 outputs/thread (rows ng, ng+8 share every
// ps load). Pure packed-f32x2 dot product, dual chains per output.
template <bool USE_PDL>
__global__ __launch_bounds__(128, 8)
void proco_kernel(const float* __restrict__ feat,
                  const float* __restrict__ logc,
                  float* __restrict__ out) {
    __shared__ __align__(16) float fs[TN][DD + 4];
    __shared__ __align__(16) float ps[TC][DD + 4];

    const int c0  = blockIdx.x * TC;
    const int n0  = blockIdx.y * TN;
    const int tid = threadIdx.x;

    // feat tile first (independent of setup): 16 rows = 512 float4
    #pragma unroll
    for (int k = 0; k < 4; ++k) {
        int i = tid + 128 * k;
        int r = i >> 5, q = i & 31;
        *reinterpret_cast<float4*>(&fs[r][4 * q]) =
            reinterpret_cast<const float4*>(feat)[(n0 + r) * (DD / 4) + q];
    }
    if (USE_PDL) asm volatile("griddepcontrol.wait;");
    #pragma unroll
    for (int k = 0; k < 4; ++k) {
        int i = tid + 128 * k;
        int r = i >> 5, q = i & 31;
        *reinterpret_cast<float4*>(&ps[r][4 * q]) =
            reinterpret_cast<const float4*>(g_proto)[(c0 + r) * (DD / 4) + q];
    }
    __syncthreads();

    const int cl = tid & 15;   // class lane (coalesced stores)
    const int ng = tid >> 4;   // thread owns n rows ng and ng+8

    unsigned long long A0 = 0ull, B0 = 0ull;  // dual chains, output 0
    unsigned long long A1 = 0ull, B1 = 0ull;  // dual chains, output 1

    #pragma unroll
    for (int grp = 0; grp < 8; ++grp) {       // 8 groups of 16 elements
        const int d0 = grp * 16;
        const ulonglong2 pa = *reinterpret_cast<const ulonglong2*>(&ps[cl][d0]);
        const ulonglong2 pb = *reinterpret_cast<const ulonglong2*>(&ps[cl][d0 + 4]);
        const ulonglong2 pc = *reinterpret_cast<const ulonglong2*>(&ps[cl][d0 + 8]);
        const ulonglong2 pd = *reinterpret_cast<const ulonglong2*>(&ps[cl][d0 + 12]);
        #define GROUP(row, A, B) {                                              \
            const ulonglong2 fa = *reinterpret_cast<const ulonglong2*>(&fs[row][d0]);      \
            const ulonglong2 fb = *reinterpret_cast<const ulonglong2*>(&fs[row][d0 + 4]);  \
            const ulonglong2 fc = *reinterpret_cast<const ulonglong2*>(&fs[row][d0 + 8]);  \
            const ulonglong2 fd = *reinterpret_cast<const ulonglong2*>(&fs[row][d0 + 12]); \
            A = fma2(pa.x, fa.x, A);                                            \
            B = fma2(pa.y, fa.y, B);                                            \
            A = fma2(pb.x, fb.x, A);                                            \
            B = fma2(pb.y, fb.y, B);                                            \
            A = fma2(pc.x, fc.x, A);                                            \
            B = fma2(pc.y, fc.y, B);                                            \
            A = fma2(pd.x, fd.x, A);                                            \
            B = fma2(pd.y, fd.y, B); }
        GROUP(ng,     A0, B0)
        GROUP(ng + 8, A1, B1)
        #undef GROUP
    }

    const int c = c0 + cl;
    if (c >= CC) return;
    const float lc = logc[c];
    const float ph = g_ph[c];
    const float pl = g_pl[c];

    #define FINISH(A, B, nrow, dst) {                                           \
        float a0, a1, b0, b1;                                                   \
        unpack2(A, a0, a1);                                                     \
        unpack2(B, b0, b1);                                                     \
        float s1, e1, s2, e2, dh, e3;                                           \
        two_sum(a0, a1, s1, e1);                                                \
        two_sum(b0, b1, s2, e2);                                                \
        two_sum(s1, s2, dh, e3);                                                \
        float dl = __fadd_rn(e1, __fadd_rn(e2, e3));                            \
        float fq = g_fsq[nrow];                                                 \
        float r  = __fadd_rn(__fmul_rn(2.0f, dh),                               \
                             __fadd_rn(__fmul_rn(2.0f, dl), fq));               \
        float s, k;                                                             \
        two_sum(ph, r, s, k);                                                   \
        k = __fadd_rn(k, pl);                                                   \
        dst = epilogue(s, k, lc);                                               \
    }
    float o0, o1;
    FINISH(A0, B0, n0 + ng,     o0)
    FINISH(A1, B1, n0 + ng + 8, o1)
    #undef FINISH
    out[(n0 + ng)     * CC + c] = o0;
    out[(n0 + ng + 8) * CC + c] = o1;
}

extern "C" void kernel_launch(void* const* d_in, const int* in_sizes, int n_in,
                              void* d_out, int out_size) {
    const float* feat  = (const float*)d_in[0];
    // d_in[1]: labels (int64) — unused by the deterministic forward math.
    const float* Ave   = (const float*)d_in[2];
    const float* kappa = (const float*)d_in[3];
    const float* logc  = (const float*)d_in[4];
    float* out = (float*)d_out;

    const dim3 grid((CC + TC - 1) / TC, NB / TN);   // (63, 16)

    // 160 blocks x 8 warps: 1024 class slots + 256 row slots
    setup_kernel<<<(CPAD + NB) / 8, 256>>>(Ave, kappa, feat);

    // PDL launch: proco may start its feat fill while setup drains.
    cudaLaunchConfig_t cfg = {};
    cfg.gridDim  = grid;
    cfg.blockDim = dim3(128, 1, 1);
    cudaLaunchAttribute at[1];
    at[0].id = cudaLaunchAttributeProgrammaticStreamSerialization;
    at[0].val.programmaticStreamSerializationAllowed = 1;
    cfg.attrs = at;
    cfg.numAttrs = 1;
    cudaError_t e = cudaLaunchKernelEx(&cfg, proco_kernel<true>, feat, logc, out);
    if (e != cudaSuccess) {
        // Fallback: plain serialized launch (twin kernel without the wait).
        proco_kernel<false><<<grid, 128>>>(feat, logc, out);
    }
}